// round 13
// baseline (speedup 1.0000x reference)
#include <cuda_runtime.h>
#include <cstdint>
#include <cstddef>

#define ORIG_IN  4096
#define ORIG_OUT 4096
#define ACTIVE   2048
#define RANK     16
#define MROWS_MAX 8192

// Packed scratch (fragment-ordered, tf32-rounded)
// XP: [MT (M/16)][KS (K/8)][lane 32][4]  -- A fragments
// WP: [NT (N/8)][KP (K/16)][lane 32][4]  -- B fragments
__device__ float g_XP[(size_t)(MROWS_MAX / 16) * (ACTIVE / 8) * 32 * 4];   // 64 MB
__device__ float g_WP[(size_t)(ACTIVE / 8) * (ACTIVE / 16) * 32 * 4];     // 16 MB

__device__ __forceinline__ unsigned smem_u32(const void* p) {
    return (unsigned)__cvta_generic_to_shared(p);
}
__device__ __forceinline__ void cp_async16(uint32_t dst, const void* src) {
    asm volatile("cp.async.cg.shared.global [%0], [%1], 16;\n" :: "r"(dst), "l"(src));
}
__device__ __forceinline__ float f2tf32f(float f) {
    uint32_t u;
    asm("cvt.rna.tf32.f32 %0, %1;" : "=r"(u) : "f"(f));
    return __uint_as_float(u);
}

// ---------------------------------------------------------------------------
// Fused pack kernel:
//   [0, ZB)            -> zero d_out (dense float4 stores; issued first so
//                         they stream out under the compute-heavy pack blocks)
//   [ZB, ZB+PW)        -> W pack (LoRA fold + tf32 + fragment order)
//   [ZB+PW, ZB+PW+PX)  -> X pack (gather + tf32 + fragment order)
// ---------------------------------------------------------------------------
#define ZB_BLOCKS 32768              // 8192*4096 floats / 4 / 256
#define PW_BLOCKS 4096
#define PX_BLOCKS 16384

__global__ void pack_fused_kernel(const float* __restrict__ x,
                                  const float* __restrict__ W_base,
                                  const float* __restrict__ lora_A,
                                  const float* __restrict__ lora_B,
                                  const int*   __restrict__ in_idx,
                                  float*       __restrict__ out,
                                  int Mrows) {
    const int bid = blockIdx.x;
    if (bid < ZB_BLOCKS) {
        // ---- zero the output ----
        size_t i4 = (size_t)bid * 256 + threadIdx.x;           // float4 index
        if (i4 < (size_t)Mrows * (ORIG_OUT / 4))
            ((float4*)out)[i4] = make_float4(0.f, 0.f, 0.f, 0.f);
    } else if (bid < ZB_BLOCKS + PW_BLOCKS) {
        // ---- pack W ----
        int gid = (bid - ZB_BLOCKS) * 256 + threadIdx.x;       // < 1,048,576
        int lane = gid & 31;
        int kp   = (gid >> 5) & 127;
        int nt   = gid >> 12;
        int g = lane >> 2, t = lane & 3;
        int n  = nt * 8 + g;
        int k0 = kp * 16 + t;

        float lb[RANK];
#pragma unroll
        for (int r = 0; r < RANK; ++r) lb[r] = __ldg(lora_B + n * RANK + r);

        const float* wrow = W_base + (size_t)n * ACTIVE;
        float outv[4];
#pragma unroll
        for (int j = 0; j < 4; ++j) {
            int k = k0 + 4 * j;
            float acc = 0.f;
#pragma unroll
            for (int r = 0; r < RANK; ++r)
                acc += lb[r] * __ldg(lora_A + r * ACTIVE + k);
            outv[j] = f2tf32f(__ldg(wrow + k) + 2.0f * acc);
        }
        *(float4*)&g_WP[(size_t)gid * 4] = *(float4*)outv;
    } else {
        // ---- pack X ----
        int gid = (bid - ZB_BLOCKS - PW_BLOCKS) * 256 + threadIdx.x;
        int total = (Mrows / 16) * (ACTIVE / 8) * 32;
        if (gid >= total) return;
        int lane = gid & 31;
        int ks   = (gid >> 5) & (ACTIVE / 8 - 1);
        int mt   = gid >> 13;
        int g = lane >> 2, t = lane & 3;
        int m0 = mt * 16 + g;
        int c0 = __ldg(in_idx + ks * 8 + t);
        int c1 = __ldg(in_idx + ks * 8 + t + 4);
        const float* r0 = x + (size_t)m0 * ORIG_IN;
        const float* r1 = x + (size_t)(m0 + 8) * ORIG_IN;
        float4 v;
        v.x = f2tf32f(__ldg(r0 + c0));
        v.y = f2tf32f(__ldg(r1 + c0));
        v.z = f2tf32f(__ldg(r0 + c1));
        v.w = f2tf32f(__ldg(r1 + c1));
        *(float4*)&g_XP[(size_t)gid * 4] = v;
    }
}

// ---------------------------------------------------------------------------
// GEMM, split-K x2: CTA (nb, mb, kz) computes the K-half [kz*1024, kz*1024+1024)
// of output tile (mb, nb) and atomicAdds it into the pre-zeroed output.
// CTA tile 128x128x32, 4 warps (warp tile 64x64), 3-stage cp.async,
// one __syncthreads per k-tile. Grid 2048 CTAs -> 6.9 waves (98.9% wave eff
// vs 86.5% at 1024 CTAs). Operand traffic unchanged (each CTA reads only
// its K-half). kz=0 contributes the bias.
// ---------------------------------------------------------------------------
#define BM 128
#define BN 128
#define BK 32
#define KSPLIT 2
#define NST 3
#define A_ST 16384                  // 8 mt * 4 ks * 512B
#define B_ST 16384                  // 16 nt * 2 kp * 512B
#define STAGE (A_ST + B_ST)         // 32 KB
#define SMEM_TOTAL (NST * STAGE)    // 96 KB

__global__ __launch_bounds__(128, 2)
void stt_gemm_kernel(const float* __restrict__ b_base,
                     const int*   __restrict__ out_idx,
                     float*       __restrict__ out,
                     int Mrows) {
    extern __shared__ char smem[];
    const uint32_t sbase = smem_u32(smem);
    const int tid  = threadIdx.x;
    const int nb   = blockIdx.x;
    const int mb   = blockIdx.y;
    const int kz   = blockIdx.z;               // K half
    const int m_base = mb * BM;
    const int n_base = nb * BN;

    const int ntiles = (ACTIVE / BK) / KSPLIT; // 32 k-tiles per CTA
    const int kt0    = kz * ntiles;            // global k-tile offset

    // stage loader: 16 x cp.async16 per thread, linear smem addressing
    auto load_stage = [&](int kt) {
        const int ktg = kt0 + kt;
        const uint32_t st = sbase + (uint32_t)(kt % NST) * STAGE;
        const float* asrc = g_XP + (((size_t)mb * 8) * (ACTIVE / 8) + (size_t)ktg * 4) * 128;
        const float* bsrc = g_WP + (((size_t)nb * 16) * (ACTIVE / 16) + (size_t)ktg * 2) * 128;
#pragma unroll
        for (int j = 0; j < 8; ++j) {
            int c = tid + 128 * j;             // 0..1023
            int mt_l = c >> 7, ks_l = (c >> 5) & 3, ln = c & 31;
            cp_async16(st + c * 16,
                       asrc + ((size_t)mt_l * (ACTIVE / 8) + ks_l) * 128 + ln * 4);
        }
#pragma unroll
        for (int j = 0; j < 8; ++j) {
            int c = tid + 128 * j;
            int nt_l = c >> 6, kp_l = (c >> 5) & 1, ln = c & 31;
            cp_async16(st + A_ST + c * 16,
                       bsrc + ((size_t)nt_l * (ACTIVE / 16) + kp_l) * 128 + ln * 4);
        }
        asm volatile("cp.async.commit_group;\n");
    };

    const int w    = tid >> 5;
    const int lane = tid & 31;
    const int wm   = w & 1;                    // 2 warps along M (64 rows each)
    const int wn   = w >> 1;                   // 2 warps along N (64 cols each)
    const int g    = lane >> 2;
    const int t    = lane & 3;

    load_stage(0);
    load_stage(1);

    float acc[4][8][4];
#pragma unroll
    for (int i = 0; i < 4; ++i)
#pragma unroll
        for (int j = 0; j < 8; ++j)
#pragma unroll
            for (int c = 0; c < 4; ++c) acc[i][j][c] = 0.f;

#pragma unroll 1
    for (int kt = 0; kt < ntiles; ++kt) {
        // Stage kt arrived (own groups): with {kt, kt+1} pending, allow 1 left.
        if (kt + 1 < ntiles) asm volatile("cp.async.wait_group 1;\n");
        else                 asm volatile("cp.async.wait_group 0;\n");
        // Barrier AFTER wait: (a) stage-kt chunks visible to all warps;
        // (b) all warps past compute(kt-1), so buffer (kt+2)%3 is free.
        __syncthreads();
        if (kt + 2 < ntiles) load_stage(kt + 2);   // drains under the MMAs below

        const char* st = (const char*)smem + (kt % NST) * STAGE;
        const char* As = st;
        const char* Bs = st + A_ST;

#pragma unroll
        for (int kp = 0; kp < 2; ++kp) {
            uint32_t bq[8][4];
#pragma unroll
            for (int nj = 0; nj < 8; ++nj) {
                float4 v = *(const float4*)(Bs + ((8 * wn + nj) * 2 + kp) * 512 + lane * 16);
                bq[nj][0] = __float_as_uint(v.x);
                bq[nj][1] = __float_as_uint(v.y);
                bq[nj][2] = __float_as_uint(v.z);
                bq[nj][3] = __float_as_uint(v.w);
            }
#pragma unroll
            for (int sp = 0; sp < 2; ++sp) {
                const int ks = kp * 2 + sp;
                uint32_t aq[4][4];
#pragma unroll
                for (int mi = 0; mi < 4; ++mi) {
                    float4 a = *(const float4*)(As + ((4 * wm + mi) * 4 + ks) * 512 + lane * 16);
                    aq[mi][0] = __float_as_uint(a.x);
                    aq[mi][1] = __float_as_uint(a.y);
                    aq[mi][2] = __float_as_uint(a.z);
                    aq[mi][3] = __float_as_uint(a.w);
                }
#pragma unroll
                for (int mi = 0; mi < 4; ++mi)
#pragma unroll
                    for (int nj = 0; nj < 8; ++nj) {
                        asm volatile(
                            "mma.sync.aligned.m16n8k8.row.col.f32.tf32.tf32.f32 "
                            "{%0,%1,%2,%3}, {%4,%5,%6,%7}, {%8,%9}, {%0,%1,%2,%3};\n"
                            : "+f"(acc[mi][nj][0]), "+f"(acc[mi][nj][1]),
                              "+f"(acc[mi][nj][2]), "+f"(acc[mi][nj][3])
                            : "r"(aq[mi][0]), "r"(aq[mi][1]),
                              "r"(aq[mi][2]), "r"(aq[mi][3]),
                              "r"(bq[nj][2 * sp]), "r"(bq[nj][2 * sp + 1]));
                    }
            }
        }
    }

    // Epilogue: atomicAdd partials into the pre-zeroed output (REDG, no
    // return). kz=0 contributes the bias; addresses of the two kz halves
    // coincide, so adds combine; everything else is disjoint.
#pragma unroll
    for (int mi = 0; mi < 4; ++mi) {
        int r0 = m_base + wm * 64 + mi * 16 + g;
        int r1 = r0 + 8;
#pragma unroll
        for (int nj = 0; nj < 8; ++nj) {
            int n  = n_base + wn * 64 + nj * 8 + 2 * t;
            int o0 = __ldg(out_idx + n);
            int o1 = __ldg(out_idx + n + 1);
            float bb0 = (kz == 0) ? __ldg(b_base + n)     : 0.f;
            float bb1 = (kz == 0) ? __ldg(b_base + n + 1) : 0.f;
            if (r0 < Mrows) {
                atomicAdd(&out[(size_t)r0 * ORIG_OUT + o0], acc[mi][nj][0] + bb0);
                atomicAdd(&out[(size_t)r0 * ORIG_OUT + o1], acc[mi][nj][1] + bb1);
            }
            if (r1 < Mrows) {
                atomicAdd(&out[(size_t)r1 * ORIG_OUT + o0], acc[mi][nj][2] + bb0);
                atomicAdd(&out[(size_t)r1 * ORIG_OUT + o1], acc[mi][nj][3] + bb1);
            }
        }
    }
}

// ---------------------------------------------------------------------------
// Launch: exactly TWO launches per call (pack_fused incl. output zero, gemm).
// ---------------------------------------------------------------------------
extern "C" void kernel_launch(void* const* d_in, const int* in_sizes, int n_in,
                              void* d_out, int out_size) {
    const float* x       = (const float*)d_in[0];
    const float* W_base  = (const float*)d_in[1];
    const float* b_base  = (const float*)d_in[2];
    const float* lora_A  = (const float*)d_in[3];
    const float* lora_B  = (const float*)d_in[4];
    const int*   in_idx  = (const int*)d_in[5];
    const int*   out_idx = (const int*)d_in[6];
    float*       out     = (float*)d_out;

    const int Mrows = in_sizes[0] / ORIG_IN;    // 8192

    pack_fused_kernel<<<ZB_BLOCKS + PW_BLOCKS + PX_BLOCKS, 256>>>(
        x, W_base, lora_A, lora_B, in_idx, out, Mrows);

    cudaFuncSetAttribute(stt_gemm_kernel,
                         cudaFuncAttributeMaxDynamicSharedMemorySize, SMEM_TOTAL);
    dim3 grid(ACTIVE / BN, (Mrows + BM - 1) / BM, KSPLIT);   // (16, 64, 2)
    stt_gemm_kernel<<<grid, 128, SMEM_TOTAL>>>(b_base, out_idx, out, Mrows);
}

// round 15
// speedup vs baseline: 1.0771x; 1.0771x over previous
#include <cuda_runtime.h>
#include <cstdint>
#include <cstddef>

#define ORIG_IN  4096
#define ORIG_OUT 4096
#define ACTIVE   2048
#define RANK     16
#define MROWS_MAX 8192

// Packed scratch (fragment-ordered, tf32-rounded)
// XP: [MT (M/16)][KS (K/8)][lane 32][4]  -- A fragments
// WP: [NT (N/8)][KP (K/16)][lane 32][4]  -- B fragments
__device__ float g_XP[(size_t)(MROWS_MAX / 16) * (ACTIVE / 8) * 32 * 4];   // 64 MB
__device__ float g_WP[(size_t)(ACTIVE / 8) * (ACTIVE / 16) * 32 * 4];     // 16 MB
// 1 if this dense output column receives a value, 0 if it must be zeroed.
// Static zero-init; marking from out_idx is idempotent across graph replays.
__device__ int g_colflag[ORIG_OUT];

__device__ __forceinline__ unsigned smem_u32(const void* p) {
    return (unsigned)__cvta_generic_to_shared(p);
}
__device__ __forceinline__ void cp_async16(uint32_t dst, const void* src) {
    asm volatile("cp.async.cg.shared.global [%0], [%1], 16;\n" :: "r"(dst), "l"(src));
}
__device__ __forceinline__ float f2tf32f(float f) {
    uint32_t u;
    asm("cvt.rna.tf32.f32 %0, %1;" : "=r"(u) : "f"(f));
    return __uint_as_float(u);
}

// ---------------------------------------------------------------------------
// Fused pack kernel:
//   [0, PW)        -> W pack; lora_A/lora_B staged in smem (kills the 71% L1
//                     redundant-broadcast LDG traffic measured in R10-12)
//   [PW, PW+PX)    -> X pack; thread owns (mtg, ks, lane), loops 8 mt blocks
//                     (idx loads amortized 8x, higher MLP)
//   PW+PX          -> mark g_colflag from out_idx
// Output layouts and arithmetic order are IDENTICAL to R12 (bitwise-same
// XP/WP).
// ---------------------------------------------------------------------------
#define PW_BLOCKS 4096
#define PX_BLOCKS 2048

__global__ void pack_fused_kernel(const float* __restrict__ x,
                                  const float* __restrict__ W_base,
                                  const float* __restrict__ lora_A,
                                  const float* __restrict__ lora_B,
                                  const int*   __restrict__ in_idx,
                                  const int*   __restrict__ out_idx,
                                  int Mrows) {
    const int bid = blockIdx.x;
    const int tid = threadIdx.x;
    if (bid < PW_BLOCKS) {
        // ---- pack W ----
        // Block geometry (from gid = bid*256 + tid):
        //   nt = bid >> 4 (constant per block), kp = (bid % 16) * 8 + (tid>>5)
        //   => block covers n rows [nt*8, nt*8+8), k range [kbase, kbase+128)
        __shared__ float sA[16 * 128];   // lora_A[r][kbase + kk]
        __shared__ float sB[8 * 16];     // lora_B[nt*8 + gg][r]
        const int nt    = bid >> 4;
        const int kbase = (bid & 15) * 128;

        // stage lora_A slice (coalesced: 2048 floats, 8 per thread)
#pragma unroll
        for (int j = 0; j < 8; ++j) {
            int i = tid + 256 * j;                   // 0..2047
            int r = i >> 7, kk = i & 127;
            sA[i] = __ldg(lora_A + r * ACTIVE + kbase + kk);
        }
        if (tid < 128) {
            int gg = tid >> 4, r = tid & 15;
            sB[tid] = __ldg(lora_B + (nt * 8 + gg) * RANK + r);
        }
        __syncthreads();

        const int gid  = bid * 256 + tid;
        const int lane = tid & 31;
        const int wid  = tid >> 5;                   // kp offset within block
        const int g = lane >> 2, t = lane & 3;
        const int n  = nt * 8 + g;
        const int kk0 = wid * 16 + t;                // k local to kbase

        float lb[RANK];
#pragma unroll
        for (int r = 0; r < RANK; ++r) lb[r] = sB[g * 16 + r];

        const float* wrow = W_base + (size_t)n * ACTIVE + kbase;
        float outv[4];
#pragma unroll
        for (int j = 0; j < 4; ++j) {
            int kk = kk0 + 4 * j;
            float acc = 0.f;
#pragma unroll
            for (int r = 0; r < RANK; ++r)
                acc += lb[r] * sA[r * 128 + kk];
            outv[j] = f2tf32f(__ldg(wrow + kk) + 2.0f * acc);
        }
        *(float4*)&g_WP[(size_t)gid * 4] = *(float4*)outv;
    } else if (bid < PW_BLOCKS + PX_BLOCKS) {
        // ---- pack X ----
        // gid in [0, 524288): lane | ks (256) | mtg (64). Loops 8 mt blocks.
        int gid  = (bid - PW_BLOCKS) * 256 + tid;
        int lane = gid & 31;
        int ks   = (gid >> 5) & 255;
        int mtg  = gid >> 13;                        // 0..63
        int g = lane >> 2, t = lane & 3;
        const int c0 = __ldg(in_idx + ks * 8 + t);
        const int c1 = __ldg(in_idx + ks * 8 + t + 4);
        const int mt_max = Mrows / 16;
#pragma unroll
        for (int i = 0; i < 8; ++i) {
            int mt = mtg * 8 + i;
            if (mt >= mt_max) break;
            int m0 = mt * 16 + g;
            const float* r0 = x + (size_t)m0 * ORIG_IN;
            const float* r1 = x + (size_t)(m0 + 8) * ORIG_IN;
            float4 v;
            v.x = f2tf32f(__ldg(r0 + c0));
            v.y = f2tf32f(__ldg(r1 + c0));
            v.z = f2tf32f(__ldg(r0 + c1));
            v.w = f2tf32f(__ldg(r1 + c1));
            *(float4*)&g_XP[(((size_t)mt * (ACTIVE / 8) + ks) * 32 + lane) * 4] = v;
        }
    } else {
        // ---- mark active output columns (idempotent) ----
        for (int i = tid; i < ACTIVE; i += 256)
            g_colflag[__ldg(out_idx + i)] = 1;
    }
}

// ---------------------------------------------------------------------------
// GEMM: 128x128x32 CTA tile, 4 warps (128 thr), warp tile 64x64.
// 3-stage cp.async pipeline, one __syncthreads per k-tile:
//   wait_group(stage kt) -> barrier -> issue load(kt+2) -> compute(kt)
// 2 CTAs/SM (96 KB smem each). Identical to R12 (best: 346.9us).
// ---------------------------------------------------------------------------
#define BM 128
#define BN 128
#define BK 32
#define NST 3
#define A_ST 16384                  // 8 mt * 4 ks * 512B
#define B_ST 16384                  // 16 nt * 2 kp * 512B
#define STAGE (A_ST + B_ST)         // 32 KB
#define SMEM_TOTAL (NST * STAGE)    // 96 KB

__global__ __launch_bounds__(128, 2)
void stt_gemm_kernel(const float* __restrict__ b_base,
                     const int*   __restrict__ out_idx,
                     float*       __restrict__ out,
                     int Mrows) {
    extern __shared__ char smem[];
    const uint32_t sbase = smem_u32(smem);
    const int tid  = threadIdx.x;
    const int nb   = blockIdx.x;
    const int mb   = blockIdx.y;
    const int m_base = mb * BM;
    const int n_base = nb * BN;

    // stage loader: 16 x cp.async16 per thread, linear smem addressing
    auto load_stage = [&](int kt) {
        const uint32_t st = sbase + (uint32_t)(kt % NST) * STAGE;
        const float* asrc = g_XP + (((size_t)mb * 8) * (ACTIVE / 8) + (size_t)kt * 4) * 128;
        const float* bsrc = g_WP + (((size_t)nb * 16) * (ACTIVE / 16) + (size_t)kt * 2) * 128;
#pragma unroll
        for (int j = 0; j < 8; ++j) {
            int c = tid + 128 * j;             // 0..1023
            int mt_l = c >> 7, ks_l = (c >> 5) & 3, ln = c & 31;
            cp_async16(st + c * 16,
                       asrc + ((size_t)mt_l * (ACTIVE / 8) + ks_l) * 128 + ln * 4);
        }
#pragma unroll
        for (int j = 0; j < 8; ++j) {
            int c = tid + 128 * j;
            int nt_l = c >> 6, kp_l = (c >> 5) & 1, ln = c & 31;
            cp_async16(st + A_ST + c * 16,
                       bsrc + ((size_t)nt_l * (ACTIVE / 16) + kp_l) * 128 + ln * 4);
        }
        asm volatile("cp.async.commit_group;\n");
    };

    const int w    = tid >> 5;
    const int lane = tid & 31;
    const int wm   = w & 1;                    // 2 warps along M (64 rows each)
    const int wn   = w >> 1;                   // 2 warps along N (64 cols each)
    const int g    = lane >> 2;
    const int t    = lane & 3;

    const int ntiles = ACTIVE / BK;            // 64
    load_stage(0);
    load_stage(1);

    // Zero the inactive dense columns of this CTA's stripe:
    // rows [m_base, m_base+128) x dense cols [nb*256, nb*256+256).
#pragma unroll
    for (int half = 0; half < 2; ++half) {
        const int c = nb * 256 + half * 128 + tid;
        if (!g_colflag[c]) {
            float* p = out + (size_t)m_base * ORIG_OUT + c;
#pragma unroll 4
            for (int r = 0; r < BM; ++r) {
                if (m_base + r < Mrows) p[0] = 0.f;
                p += ORIG_OUT;
            }
        }
    }

    float acc[4][8][4];
#pragma unroll
    for (int i = 0; i < 4; ++i)
#pragma unroll
        for (int j = 0; j < 8; ++j)
#pragma unroll
            for (int c = 0; c < 4; ++c) acc[i][j][c] = 0.f;

#pragma unroll 1
    for (int kt = 0; kt < ntiles; ++kt) {
        if (kt + 1 < ntiles) asm volatile("cp.async.wait_group 1;\n");
        else                 asm volatile("cp.async.wait_group 0;\n");
        __syncthreads();
        if (kt + 2 < ntiles) load_stage(kt + 2);   // drains under the MMAs below

        const char* st = (const char*)smem + (kt % NST) * STAGE;
        const char* As = st;
        const char* Bs = st + A_ST;

#pragma unroll
        for (int kp = 0; kp < 2; ++kp) {
            uint32_t bq[8][4];
#pragma unroll
            for (int nj = 0; nj < 8; ++nj) {
                float4 v = *(const float4*)(Bs + ((8 * wn + nj) * 2 + kp) * 512 + lane * 16);
                bq[nj][0] = __float_as_uint(v.x);
                bq[nj][1] = __float_as_uint(v.y);
                bq[nj][2] = __float_as_uint(v.z);
                bq[nj][3] = __float_as_uint(v.w);
            }
#pragma unroll
            for (int sp = 0; sp < 2; ++sp) {
                const int ks = kp * 2 + sp;
                uint32_t aq[4][4];
#pragma unroll
                for (int mi = 0; mi < 4; ++mi) {
                    float4 a = *(const float4*)(As + ((4 * wm + mi) * 4 + ks) * 512 + lane * 16);
                    aq[mi][0] = __float_as_uint(a.x);
                    aq[mi][1] = __float_as_uint(a.y);
                    aq[mi][2] = __float_as_uint(a.z);
                    aq[mi][3] = __float_as_uint(a.w);
                }
#pragma unroll
                for (int mi = 0; mi < 4; ++mi)
#pragma unroll
                    for (int nj = 0; nj < 8; ++nj) {
                        asm volatile(
                            "mma.sync.aligned.m16n8k8.row.col.f32.tf32.tf32.f32 "
                            "{%0,%1,%2,%3}, {%4,%5,%6,%7}, {%8,%9}, {%0,%1,%2,%3};\n"
                            : "+f"(acc[mi][nj][0]), "+f"(acc[mi][nj][1]),
                              "+f"(acc[mi][nj][2]), "+f"(acc[mi][nj][3])
                            : "r"(aq[mi][0]), "r"(aq[mi][1]),
                              "r"(aq[mi][2]), "r"(aq[mi][3]),
                              "r"(bq[nj][2 * sp]), "r"(bq[nj][2 * sp + 1]));
                    }
            }
        }
    }

    // Epilogue: bias add + scatter through out_idx.
#pragma unroll
    for (int mi = 0; mi < 4; ++mi) {
        int r0 = m_base + wm * 64 + mi * 16 + g;
        int r1 = r0 + 8;
#pragma unroll
        for (int nj = 0; nj < 8; ++nj) {
            int n  = n_base + wn * 64 + nj * 8 + 2 * t;
            int o0 = __ldg(out_idx + n);
            int o1 = __ldg(out_idx + n + 1);
            float bb0 = __ldg(b_base + n);
            float bb1 = __ldg(b_base + n + 1);
            if (r0 < Mrows) {
                out[(size_t)r0 * ORIG_OUT + o0] = acc[mi][nj][0] + bb0;
                out[(size_t)r0 * ORIG_OUT + o1] = acc[mi][nj][1] + bb1;
            }
            if (r1 < Mrows) {
                out[(size_t)r1 * ORIG_OUT + o0] = acc[mi][nj][2] + bb0;
                out[(size_t)r1 * ORIG_OUT + o1] = acc[mi][nj][3] + bb1;
            }
        }
    }
}

// ---------------------------------------------------------------------------
// Launch: exactly TWO launches per call (pack_fused, gemm).
// ---------------------------------------------------------------------------
extern "C" void kernel_launch(void* const* d_in, const int* in_sizes, int n_in,
                              void* d_out, int out_size) {
    const float* x       = (const float*)d_in[0];
    const float* W_base  = (const float*)d_in[1];
    const float* b_base  = (const float*)d_in[2];
    const float* lora_A  = (const float*)d_in[3];
    const float* lora_B  = (const float*)d_in[4];
    const int*   in_idx  = (const int*)d_in[5];
    const int*   out_idx = (const int*)d_in[6];
    float*       out     = (float*)d_out;

    const int Mrows = in_sizes[0] / ORIG_IN;    // 8192

    pack_fused_kernel<<<PW_BLOCKS + PX_BLOCKS + 1, 256>>>(
        x, W_base, lora_A, lora_B, in_idx, out_idx, Mrows);

    cudaFuncSetAttribute(stt_gemm_kernel,
                         cudaFuncAttributeMaxDynamicSharedMemorySize, SMEM_TOTAL);
    dim3 grid(ACTIVE / BN, (Mrows + BM - 1) / BM);   // (16, 64): N fastest
    stt_gemm_kernel<<<grid, 128, SMEM_TOTAL>>>(b_base, out_idx, out, Mrows);
}